// round 7
// baseline (speedup 1.0000x reference)
#include <cuda_runtime.h>
#include <math.h>

#define LN2F 0.69314718055994530942f
#define MAXB 64
#define BLK 256

// Device-global accumulators: zero-initialized at module load; the final
// block resets them after reading, so every graph replay starts clean.
__device__ double       g_cls_sum[MAXB];
__device__ double       g_reg_sum[MAXB];
__device__ int          g_num_pos[MAXB];
__device__ unsigned int g_ticket;

__device__ __forceinline__ float rsqrt_fast(float x) {
    float r;
    asm("rsqrt.approx.f32 %0, %1;" : "=f"(r) : "f"(x));
    return r;
}

__device__ __forceinline__ float smooth_l1(float d) {
    float ad = fabsf(d);
    return (ad <= (1.0f / 9.0f)) ? (4.5f * ad * ad) : (ad - 0.5f / 9.0f);
}

template<int C>
__global__ void __launch_bounds__(BLK)
focal_fused_kernel(const float* __restrict__ cls,
                   const float* __restrict__ reg,
                   const float* __restrict__ anchors,
                   const float* __restrict__ ann,
                   float* __restrict__ out,
                   int A, int M, int B, int Cdyn, int nblocks)
{
    const int img = blockIdx.y;
    const int a   = blockIdx.x * BLK + threadIdx.x;
    const int CC  = (C > 0) ? C : Cdyn;

    __shared__ float4 sbox[32];
    __shared__ float  sar[32];
    __shared__ int    slbl[32];
    __shared__ int    sMc;

    // Warp 0 compacts valid GT boxes (M <= 32 here) via ballot.
    if (threadIdx.x < 32) {
        int m = threadIdx.x;
        bool v = false;
        float x1 = 0.f, y1 = 0.f, x2 = 0.f, y2 = 0.f, l = -1.f;
        if (m < M) {
            const float* p = ann + ((size_t)img * M + m) * 5;
            x1 = p[0]; y1 = p[1]; x2 = p[2]; y2 = p[3]; l = p[4];
            v = (l != -1.0f);
        }
        unsigned mask = __ballot_sync(0xffffffffu, v);
        if (v) {
            int cpos = __popc(mask & ((1u << m) - 1u));
            sbox[cpos] = make_float4(x1, y1, x2, y2);
            sar[cpos]  = (x2 - x1) * (y2 - y1);
            slbl[cpos] = (int)l;
        }
        if (m == 0) sMc = __popc(mask);
    }
    __syncthreads();
    const int Mc = sMc;

    float cls_acc = 0.0f;
    float reg_acc = 0.0f;
    int   pos_cnt = 0;

    if (a < A) {
        float4 anc = __ldg((const float4*)anchors + a);
        float aw = anc.z - anc.x;
        float ah = anc.w - anc.y;
        float area_a = aw * ah;

        // IoU max/argmax without per-iter division: track (inter, ua) of best.
        // ua > 0 always (union of boxes with positive dims), so cross-multiply
        // comparison preserves ordering even for negative inter values, and
        // negative/zero "iou" candidates can never be classified positive.
        float bi = -1.0f, bu = 1.0f;
        int   barg = 0;
        #pragma unroll 4
        for (int m = 0; m < Mc; m++) {
            float4 b = sbox[m];
            float iw = fminf(anc.z, b.z) - fmaxf(anc.x, b.x);
            float ih = fminf(anc.w, b.w) - fmaxf(anc.y, b.y);
            float inter = fmaxf(iw, 0.0f) * ih;
            float ua = (area_a + sar[m]) - inter;
            if (inter * bu > bi * ua) { bi = inter; bu = ua; barg = m; }
        }
        float ioumax = bi / bu;               // exact rn division once
        bool pos = (ioumax >= 0.5f);
        bool contrib = pos | (ioumax < 0.4f); // skip ignore band entirely

        if (contrib) {
            float acc = 0.0f;                 // sum of p^1.5 * log2(1-p)
            if (C > 0) {
                const float4* cp = (const float4*)(cls + ((size_t)img * A + a) * C);
                #pragma unroll
                for (int j = 0; j < C / 4; j++) {
                    float4 v = cp[j];
                    { float p = v.x; acc = fmaf(p * p * rsqrt_fast(p), __log2f(1.0f - p), acc); }
                    { float p = v.y; acc = fmaf(p * p * rsqrt_fast(p), __log2f(1.0f - p), acc); }
                    { float p = v.z; acc = fmaf(p * p * rsqrt_fast(p), __log2f(1.0f - p), acc); }
                    { float p = v.w; acc = fmaf(p * p * rsqrt_fast(p), __log2f(1.0f - p), acc); }
                }
            } else {
                const float* cp = cls + ((size_t)img * A + a) * CC;
                for (int j = 0; j < CC; j++) {
                    float p = cp[j];
                    acc = fmaf(p * p * rsqrt_fast(p), __log2f(1.0f - p), acc);
                }
            }
            if (pos) {
                // Correct the single labeled class: remove its negative-form
                // term, add the positive-form term (alpha = 0.2).
                int lbl = slbl[barg];
                float p  = __ldg(cls + ((size_t)img * A + a) * CC + lbl);
                float wl = p * p * rsqrt_fast(p) * __log2f(1.0f - p);
                float q  = 1.0f - p;
                float ql = q * q * rsqrt_fast(q) * __log2f(p);
                cls_acc = -LN2F * (0.8f * (acc - wl) + 0.2f * ql);
            } else {
                cls_acc = (-0.8f * LN2F) * acc;
            }
        }

        if (pos) {
            pos_cnt = 1;
            float4 r = __ldg((const float4*)reg + (size_t)img * A + a);
            float4 b = sbox[barg];
            float gwr = b.z - b.x, ghr = b.w - b.y;
            float gcx = b.x + 0.5f * gwr, gcy = b.y + 0.5f * ghr;
            float gw = fmaxf(gwr, 1.0f), gh = fmaxf(ghr, 1.0f);
            float acx = anc.x + 0.5f * aw, acy = anc.y + 0.5f * ah;
            float rt0 = ((gcx - acx) / aw) * 10.0f;
            float rt1 = ((gcy - acy) / ah) * 10.0f;
            float rt2 = __logf(gw / aw) * 5.0f;
            float rt3 = __logf(gh / ah) * 5.0f;
            reg_acc = smooth_l1(rt0 - r.x) + smooth_l1(rt1 - r.y) +
                      smooth_l1(rt2 - r.z) + smooth_l1(rt3 - r.w);
        }
    }

    // ---- block reduction ----
    #pragma unroll
    for (int off = 16; off > 0; off >>= 1) {
        cls_acc += __shfl_down_sync(0xFFFFFFFFu, cls_acc, off);
        reg_acc += __shfl_down_sync(0xFFFFFFFFu, reg_acc, off);
        pos_cnt += __shfl_down_sync(0xFFFFFFFFu, pos_cnt, off);
    }
    __shared__ float s_cls[BLK / 32], s_reg[BLK / 32];
    __shared__ int   s_pos[BLK / 32];
    int wid  = threadIdx.x >> 5;
    int lane = threadIdx.x & 31;
    if (lane == 0) { s_cls[wid] = cls_acc; s_reg[wid] = reg_acc; s_pos[wid] = pos_cnt; }
    __syncthreads();
    if (wid == 0) {
        cls_acc = (lane < BLK / 32) ? s_cls[lane] : 0.0f;
        reg_acc = (lane < BLK / 32) ? s_reg[lane] : 0.0f;
        pos_cnt = (lane < BLK / 32) ? s_pos[lane] : 0;
        #pragma unroll
        for (int off = 4; off > 0; off >>= 1) {
            cls_acc += __shfl_down_sync(0xFFFFFFFFu, cls_acc, off);
            reg_acc += __shfl_down_sync(0xFFFFFFFFu, reg_acc, off);
            pos_cnt += __shfl_down_sync(0xFFFFFFFFu, pos_cnt, off);
        }
        if (lane == 0) {
            if (cls_acc != 0.0f) atomicAdd(&g_cls_sum[img], (double)cls_acc);
            if (reg_acc != 0.0f) atomicAdd(&g_reg_sum[img], (double)reg_acc);
            if (pos_cnt)         atomicAdd(&g_num_pos[img], pos_cnt);
        }
    }

    // ---- last-block finalize (fused; self-resets accumulators) ----
    __shared__ bool is_last;
    if (threadIdx.x == 0) {
        __threadfence();
        unsigned t = atomicAdd(&g_ticket, 1u);
        is_last = (t == (unsigned)(nblocks - 1));
    }
    __syncthreads();
    if (is_last) {
        __threadfence();
        __shared__ float fcl[MAXB], frl[MAXB];
        if (threadIdx.x < B) {
            int i = threadIdx.x;
            int nv = 0;
            for (int m = 0; m < M; m++)
                nv += (ann[((size_t)i * M + m) * 5 + 4] != -1.0f) ? 1 : 0;
            int np = g_num_pos[i];
            double npd = (np > 0) ? (double)np : 1.0;
            fcl[i] = (nv > 0) ? (float)(g_cls_sum[i] / npd) : 0.0f;
            frl[i] = (nv > 0 && np > 0) ? (float)(g_reg_sum[i] / (4.0 * (double)np)) : 0.0f;
            g_cls_sum[i] = 0.0;
            g_reg_sum[i] = 0.0;
            g_num_pos[i] = 0;
        }
        __syncthreads();
        if (threadIdx.x == 0) {
            float cs = 0.0f, rs = 0.0f;
            for (int b2 = 0; b2 < B; b2++) { cs += fcl[b2]; rs += frl[b2]; }
            out[0] = cs / (float)B;
            out[1] = rs / (float)B;
            __threadfence();
            g_ticket = 0;
        }
    }
}

extern "C" void kernel_launch(void* const* d_in, const int* in_sizes, int n_in,
                              void* d_out, int out_size)
{
    const float* cls     = (const float*)d_in[0];
    const float* reg     = (const float*)d_in[1];
    const float* anchors = (const float*)d_in[2];
    const float* ann     = (const float*)d_in[3];

    int A = in_sizes[2] / 4;                                     // anchors [1,A,4]
    int B = in_sizes[1] / (A * 4);                               // regressions [B,A,4]
    int C = (int)((long long)in_sizes[0] / ((long long)B * A));  // cls [B,A,C]
    int M = in_sizes[3] / (B * 5);                               // annotations [B,M,5]

    dim3 grid((A + BLK - 1) / BLK, B);
    int nblocks = grid.x * grid.y;

    if (C == 20) {
        focal_fused_kernel<20><<<grid, BLK>>>(cls, reg, anchors, ann,
                                              (float*)d_out, A, M, B, C, nblocks);
    } else {
        focal_fused_kernel<0><<<grid, BLK>>>(cls, reg, anchors, ann,
                                             (float*)d_out, A, M, B, C, nblocks);
    }
}